// round 1
// baseline (speedup 1.0000x reference)
#include <cuda_runtime.h>
#include <math.h>

#define N_NODES 50000
#define N_EDGES 800000
#define F0 128
#define F1 96
#define F2 96
#define F3 40

// ---------------- scratch (static device globals; no allocation) ----------------
__device__ int   g_is64;
__device__ int   g_deg[N_NODES];
__device__ int   g_cur[N_NODES];
__device__ int   g_off[N_NODES + 1];
__device__ int   g_csr[N_EDGES];
__device__ float g_agg1[(size_t)N_NODES * F0];
__device__ float g_h1  [(size_t)N_NODES * F1];
__device__ float g_agg2[(size_t)N_NODES * F1];
__device__ float g_h2  [(size_t)N_NODES * F2];
__device__ float g_agg3[(size_t)N_NODES * F2];

// ---------------- edge-index dtype detection (int64 vs int32) ----------------
// int64 values < 50000 -> every odd 32-bit word of the first 128 values is 0.
// int32 random values in [0,50000): P(127 consecutive zeros) ~ 0.
__global__ void detect_kernel(const int* __restrict__ ei) {
    if (threadIdx.x == 0 && blockIdx.x == 0) {
        int acc = 0;
#pragma unroll
        for (int i = 1; i < 255; i += 2) acc |= ei[i];
        g_is64 = (acc == 0) ? 1 : 0;
    }
}

__device__ __forceinline__ int edge_src(const int* ei, int e, int is64) {
    return is64 ? ei[2 * e] : ei[e];
}
__device__ __forceinline__ int edge_dst(const int* ei, int e, int is64) {
    return is64 ? ei[2 * (N_EDGES + e)] : ei[N_EDGES + e];
}

// ---------------- CSR build ----------------
__global__ void zero_deg_kernel() {
    int i = blockIdx.x * blockDim.x + threadIdx.x;
    if (i < N_NODES) g_deg[i] = 0;
}

__global__ void hist_kernel(const int* __restrict__ ei) {
    int e = blockIdx.x * blockDim.x + threadIdx.x;
    if (e >= N_EDGES) return;
    int is64 = g_is64;
    atomicAdd(&g_deg[edge_dst(ei, e, is64)], 1);
}

// single-block chunked Hillis-Steele scan over 50000 degrees
__global__ void scan_kernel() {
    __shared__ int sh[1024];
    __shared__ int s_carry;
    if (threadIdx.x == 0) { s_carry = 0; g_off[0] = 0; }
    __syncthreads();
    for (int base = 0; base < N_NODES; base += 1024) {
        int i = base + threadIdx.x;
        int v = (i < N_NODES) ? g_deg[i] : 0;
        sh[threadIdx.x] = v;
        __syncthreads();
        for (int s = 1; s < 1024; s <<= 1) {
            int t = (threadIdx.x >= s) ? sh[threadIdx.x - s] : 0;
            __syncthreads();
            sh[threadIdx.x] += t;
            __syncthreads();
        }
        int incl = sh[threadIdx.x];
        if (i < N_NODES) {
            g_off[i + 1] = s_carry + incl;       // inclusive -> off[i+1]
            g_cur[i]     = s_carry + incl - v;   // exclusive -> scatter cursor
        }
        __syncthreads();
        if (threadIdx.x == 1023) s_carry += incl;
        __syncthreads();
    }
}

__global__ void scatter_kernel(const int* __restrict__ ei) {
    int e = blockIdx.x * blockDim.x + threadIdx.x;
    if (e >= N_EDGES) return;
    int is64 = g_is64;
    int d = edge_dst(ei, e, is64);
    int s = edge_src(ei, e, is64);
    int p = atomicAdd(&g_cur[d], 1);
    g_csr[p] = s;
}

// ---------------- gather-side aggregation: 1 warp per node, float4 lanes ----------------
template <int D>
__global__ void agg_kernel(const float* __restrict__ xin, float* __restrict__ xout) {
    int gw   = (blockIdx.x * blockDim.x + threadIdx.x) >> 5;
    int lane = threadIdx.x & 31;
    if (gw >= N_NODES) return;
    constexpr int D4 = D / 4;
    float4 acc = make_float4(0.f, 0.f, 0.f, 0.f);
    int beg = g_off[gw], end = g_off[gw + 1];
    int e = beg;
    for (; e + 1 < end; e += 2) {
        int s0 = g_csr[e], s1 = g_csr[e + 1];
        if (lane < D4) {
            float4 v0 = __ldg((const float4*)(xin + (size_t)s0 * D) + lane);
            float4 v1 = __ldg((const float4*)(xin + (size_t)s1 * D) + lane);
            acc.x += v0.x + v1.x; acc.y += v0.y + v1.y;
            acc.z += v0.z + v1.z; acc.w += v0.w + v1.w;
        }
    }
    if (e < end) {
        int s0 = g_csr[e];
        if (lane < D4) {
            float4 v0 = __ldg((const float4*)(xin + (size_t)s0 * D) + lane);
            acc.x += v0.x; acc.y += v0.y; acc.z += v0.z; acc.w += v0.w;
        }
    }
    if (lane < D4) ((float4*)(xout + (size_t)gw * D))[lane] = acc;
}

// ---------------- dense linear + bias (+ReLU): W staged in shared ----------------
// block: (M/4, ROWS). thread computes 4 output cols of one row.
template <int K, int M, int ROWS, bool RELU>
__global__ void gemm_kernel(const float* __restrict__ X, const float* __restrict__ W,
                            const float* __restrict__ b, float* __restrict__ Y) {
    constexpr int M4 = M / 4;
    __shared__ float4 sW[K * M4];
    int tid  = threadIdx.y * blockDim.x + threadIdx.x;
    int nthr = blockDim.x * blockDim.y;
    for (int i = tid; i < K * M4; i += nthr) sW[i] = ((const float4*)W)[i];
    __syncthreads();
    int row = blockIdx.x * ROWS + threadIdx.y;
    if (row >= N_NODES) return;
    int cg = threadIdx.x;
    const float* xr = X + (size_t)row * K;
    float4 acc = ((const float4*)b)[cg];
#pragma unroll 8
    for (int k = 0; k < K; k++) {
        float a  = __ldg(xr + k);
        float4 w = sW[k * M4 + cg];
        acc.x += a * w.x; acc.y += a * w.y;
        acc.z += a * w.z; acc.w += a * w.w;
    }
    if (RELU) {
        acc.x = fmaxf(acc.x, 0.f); acc.y = fmaxf(acc.y, 0.f);
        acc.z = fmaxf(acc.z, 0.f); acc.w = fmaxf(acc.w, 0.f);
    }
    ((float4*)(Y + (size_t)row * M))[cg] = acc;
}

// ---------------- final: GEMM(96->40) + bias + log_softmax, 1 warp per row ----------------
__global__ void final_kernel(const float* __restrict__ W3, const float* __restrict__ b3,
                             float* __restrict__ out) {
    __shared__ float sW[F2 * F3];  // 96*40*4 = 15360 B
    for (int i = threadIdx.x; i < F2 * F3; i += blockDim.x) sW[i] = W3[i];
    __syncthreads();
    int warp = (blockIdx.x * blockDim.x + threadIdx.x) >> 5;
    int lane = threadIdx.x & 31;
    if (warp >= N_NODES) return;
    const float* xr = g_agg3 + (size_t)warp * F2;
    float acc0 = b3[lane];                              // cols 0..31
    float acc1 = (lane < 8) ? b3[lane + 32] : 0.f;      // cols 32..39
#pragma unroll 4
    for (int k = 0; k < F2; k++) {
        float a = __ldg(xr + k);
        acc0 += a * sW[k * F3 + lane];
        if (lane < 8) acc1 += a * sW[k * F3 + lane + 32];
    }
    // log_softmax over 40 values spread across the warp
    float m = fmaxf(acc0, (lane < 8) ? acc1 : -INFINITY);
#pragma unroll
    for (int o = 16; o > 0; o >>= 1) m = fmaxf(m, __shfl_xor_sync(0xffffffffu, m, o));
    float s = expf(acc0 - m) + ((lane < 8) ? expf(acc1 - m) : 0.f);
#pragma unroll
    for (int o = 16; o > 0; o >>= 1) s += __shfl_xor_sync(0xffffffffu, s, o);
    float l = logf(s);
    float* orow = out + (size_t)warp * F3;
    orow[lane] = acc0 - m - l;
    if (lane < 8) orow[lane + 32] = acc1 - m - l;
}

// ---------------- launch ----------------
extern "C" void kernel_launch(void* const* d_in, const int* in_sizes, int n_in,
                              void* d_out, int out_size) {
    const float* x  = (const float*)d_in[0];
    const float* W1 = (const float*)d_in[1];
    const float* b1 = (const float*)d_in[2];
    const float* W2 = (const float*)d_in[3];
    const float* b2 = (const float*)d_in[4];
    const float* W3 = (const float*)d_in[5];
    const float* b3 = (const float*)d_in[6];
    const int*   ei = (const int*)d_in[7];
    float* out = (float*)d_out;

    float *p_agg1, *p_h1, *p_agg2, *p_h2;
    cudaGetSymbolAddress((void**)&p_agg1, g_agg1);
    cudaGetSymbolAddress((void**)&p_h1,   g_h1);
    cudaGetSymbolAddress((void**)&p_agg2, g_agg2);
    cudaGetSymbolAddress((void**)&p_h2,   g_h2);
    float* p_agg3;
    cudaGetSymbolAddress((void**)&p_agg3, g_agg3);

    detect_kernel<<<1, 32>>>(ei);
    zero_deg_kernel<<<(N_NODES + 255) / 256, 256>>>();
    hist_kernel<<<(N_EDGES + 255) / 256, 256>>>(ei);
    scan_kernel<<<1, 1024>>>();
    scatter_kernel<<<(N_EDGES + 255) / 256, 256>>>(ei);

    const int agg_grid = (N_NODES * 32 + 255) / 256;

    // layer 1: aggregate(x) -> agg1 ; relu(agg1 @ W1 + b1) -> h1
    agg_kernel<F0><<<agg_grid, 256>>>(x, p_agg1);
    gemm_kernel<F0, F1, 10, true><<<(N_NODES + 9) / 10, dim3(F1 / 4, 10)>>>(p_agg1, W1, b1, p_h1);

    // layer 2
    agg_kernel<F1><<<agg_grid, 256>>>(p_h1, p_agg2);
    gemm_kernel<F1, F2, 10, true><<<(N_NODES + 9) / 10, dim3(F2 / 4, 10)>>>(p_agg2, W2, b2, p_h2);

    // layer 3 + log_softmax
    agg_kernel<F2><<<agg_grid, 256>>>(p_h2, p_agg3);
    final_kernel<<<agg_grid, 256>>>(W3, b3, out);
}

// round 2
// speedup vs baseline: 1.5628x; 1.5628x over previous
#include <cuda_runtime.h>
#include <math.h>

#define N_NODES 50000
#define N_EDGES 800000
#define F0 128
#define F1 96
#define F2 96
#define F3 40
#define NB ((N_NODES + 1023) / 1024)   // 49 scan blocks

// ---------------- scratch (static device globals; no allocation) ----------------
__device__ int   g_is64;
__device__ int   g_deg[N_NODES];
__device__ int   g_cur[N_NODES];
__device__ int   g_off[N_NODES + 1];
__device__ int   g_csr[N_EDGES];
__device__ int   g_bsum[NB];
__device__ int   g_boff[NB];
__device__ float g_agg1[(size_t)N_NODES * F0];
__device__ float g_h1  [(size_t)N_NODES * F1];
__device__ float g_agg2[(size_t)N_NODES * F1];
__device__ float g_h2  [(size_t)N_NODES * F2];
__device__ float g_agg3[(size_t)N_NODES * F2];

// ---------------- edge-index dtype detection (int64 vs int32) ----------------
// int64 values < 50000 -> every odd 32-bit word of the first 128 values is 0.
__global__ void detect_kernel(const int* __restrict__ ei) {
    int lane = threadIdx.x & 31;
    int acc = 0;
#pragma unroll
    for (int j = 0; j < 4; j++) acc |= ei[1 + 2 * (lane * 4 + j)];
#pragma unroll
    for (int o = 16; o > 0; o >>= 1) acc |= __shfl_xor_sync(0xffffffffu, acc, o);
    if (lane == 0) g_is64 = (acc == 0) ? 1 : 0;
}

__device__ __forceinline__ int edge_src(const int* ei, int e, int is64) {
    return is64 ? ei[2 * e] : ei[e];
}
__device__ __forceinline__ int edge_dst(const int* ei, int e, int is64) {
    return is64 ? ei[2 * (N_EDGES + e)] : ei[N_EDGES + e];
}

// ---------------- CSR build ----------------
__global__ void zero_deg_kernel() {
    int i = blockIdx.x * blockDim.x + threadIdx.x;
    if (i < N_NODES) g_deg[i] = 0;
}

__global__ void hist_kernel(const int* __restrict__ ei) {
    int e = blockIdx.x * blockDim.x + threadIdx.x;
    if (e >= N_EDGES) return;
    int is64 = g_is64;
    atomicAdd(&g_deg[edge_dst(ei, e, is64)], 1);
}

// --- 3-phase multi-block exclusive scan of g_deg -> g_off / g_cur ---
__global__ void block_sum_kernel() {
    __shared__ int wsum[32];
    int i = blockIdx.x * 1024 + threadIdx.x;
    int v = (i < N_NODES) ? g_deg[i] : 0;
    int lane = threadIdx.x & 31, w = threadIdx.x >> 5;
#pragma unroll
    for (int o = 16; o > 0; o >>= 1) v += __shfl_xor_sync(0xffffffffu, v, o);
    if (lane == 0) wsum[w] = v;
    __syncthreads();
    if (w == 0) {
        int s = wsum[lane];
#pragma unroll
        for (int o = 16; o > 0; o >>= 1) s += __shfl_xor_sync(0xffffffffu, s, o);
        if (lane == 0) g_bsum[blockIdx.x] = s;
    }
}

__global__ void scan_bsums_kernel() {   // 1 block, 64 threads, NB<=64
    __shared__ int sh[64];
    int t = threadIdx.x;
    int v = (t < NB) ? g_bsum[t] : 0;
    sh[t] = v;
    __syncthreads();
#pragma unroll
    for (int s = 1; s < 64; s <<= 1) {
        int u = (t >= s) ? sh[t - s] : 0;
        __syncthreads();
        sh[t] += u;
        __syncthreads();
    }
    if (t < NB) g_boff[t] = sh[t] - v;   // exclusive
}

__global__ void local_scan_kernel() {
    __shared__ int wsum[32];
    int i = blockIdx.x * 1024 + threadIdx.x;
    int v = (i < N_NODES) ? g_deg[i] : 0;
    int lane = threadIdx.x & 31, w = threadIdx.x >> 5;
    int incl = v;
#pragma unroll
    for (int o = 1; o < 32; o <<= 1) {
        int t = __shfl_up_sync(0xffffffffu, incl, o);
        if (lane >= o) incl += t;
    }
    if (lane == 31) wsum[w] = incl;
    __syncthreads();
    if (w == 0) {
        int s = wsum[lane];
#pragma unroll
        for (int o = 1; o < 32; o <<= 1) {
            int t = __shfl_up_sync(0xffffffffu, s, o);
            if (lane >= o) s += t;
        }
        wsum[lane] = s;
    }
    __syncthreads();
    int add = ((w > 0) ? wsum[w - 1] : 0) + g_boff[blockIdx.x];
    incl += add;
    if (i < N_NODES) {
        g_off[i + 1] = incl;
        g_cur[i]     = incl - v;
    }
    if (i == 0) g_off[0] = 0;
}

__global__ void scatter_kernel(const int* __restrict__ ei) {
    int e = blockIdx.x * blockDim.x + threadIdx.x;
    if (e >= N_EDGES) return;
    int is64 = g_is64;
    int d = edge_dst(ei, e, is64);
    int s = edge_src(ei, e, is64);
    int p = atomicAdd(&g_cur[d], 1);
    g_csr[p] = s;
}

// ---------------- gather-side aggregation: 1 warp per node, float4 lanes ----------------
template <int D>
__global__ void agg_kernel(const float* __restrict__ xin, float* __restrict__ xout) {
    int gw   = (blockIdx.x * blockDim.x + threadIdx.x) >> 5;
    int lane = threadIdx.x & 31;
    if (gw >= N_NODES) return;
    constexpr int D4 = D / 4;
    float4 acc = make_float4(0.f, 0.f, 0.f, 0.f);
    int beg = g_off[gw], end = g_off[gw + 1];
    int e = beg;
    for (; e + 3 < end; e += 4) {
        int s0 = g_csr[e], s1 = g_csr[e + 1], s2 = g_csr[e + 2], s3 = g_csr[e + 3];
        if (lane < D4) {
            float4 v0 = __ldg((const float4*)(xin + (size_t)s0 * D) + lane);
            float4 v1 = __ldg((const float4*)(xin + (size_t)s1 * D) + lane);
            float4 v2 = __ldg((const float4*)(xin + (size_t)s2 * D) + lane);
            float4 v3 = __ldg((const float4*)(xin + (size_t)s3 * D) + lane);
            acc.x += (v0.x + v1.x) + (v2.x + v3.x);
            acc.y += (v0.y + v1.y) + (v2.y + v3.y);
            acc.z += (v0.z + v1.z) + (v2.z + v3.z);
            acc.w += (v0.w + v1.w) + (v2.w + v3.w);
        }
    }
    for (; e < end; e++) {
        int s0 = g_csr[e];
        if (lane < D4) {
            float4 v0 = __ldg((const float4*)(xin + (size_t)s0 * D) + lane);
            acc.x += v0.x; acc.y += v0.y; acc.z += v0.z; acc.w += v0.w;
        }
    }
    if (lane < D4) ((float4*)(xout + (size_t)gw * D))[lane] = acc;
}

// ---------------- dense linear + bias (+ReLU): W in shared, 4 rows/thread ----------------
// block: (M/4, 8). thread computes 4 output cols x 4 rows -> 16 FMAs per sW LDS.
template <int K, int M, bool RELU>
__global__ void gemm_kernel(const float* __restrict__ X, const float* __restrict__ W,
                            const float* __restrict__ b, float* __restrict__ Y) {
    constexpr int M4  = M / 4;
    constexpr int YR  = 8;
    constexpr int RPT = 4;
    constexpr int ROWS = YR * RPT;  // 32 rows per block
    __shared__ float4 sW[K * M4];
    int tid = threadIdx.y * M4 + threadIdx.x;
    for (int i = tid; i < K * M4; i += M4 * YR) sW[i] = ((const float4*)W)[i];
    __syncthreads();

    int cg = threadIdx.x;
    int row0 = blockIdx.x * ROWS + threadIdx.y;
    float4 bias = ((const float4*)b)[cg];
    float4 acc[RPT];
    const float* xr[RPT];
    bool valid[RPT];
#pragma unroll
    for (int r = 0; r < RPT; r++) {
        int row = row0 + r * YR;
        valid[r] = (row < N_NODES);
        int rc = valid[r] ? row : (N_NODES - 1);
        xr[r] = X + (size_t)rc * K;
        acc[r] = bias;
    }
#pragma unroll 4
    for (int k = 0; k < K; k++) {
        float4 w = sW[k * M4 + cg];
#pragma unroll
        for (int r = 0; r < RPT; r++) {
            float a = __ldg(xr[r] + k);
            acc[r].x += a * w.x; acc[r].y += a * w.y;
            acc[r].z += a * w.z; acc[r].w += a * w.w;
        }
    }
#pragma unroll
    for (int r = 0; r < RPT; r++) {
        if (!valid[r]) continue;
        float4 o = acc[r];
        if (RELU) {
            o.x = fmaxf(o.x, 0.f); o.y = fmaxf(o.y, 0.f);
            o.z = fmaxf(o.z, 0.f); o.w = fmaxf(o.w, 0.f);
        }
        ((float4*)(Y + (size_t)(row0 + r * YR) * M))[cg] = o;
    }
}

// ---------------- final: GEMM(96->40) + bias + log_softmax, 1 warp per row ----------------
__global__ void final_kernel(const float* __restrict__ W3, const float* __restrict__ b3,
                             float* __restrict__ out) {
    __shared__ float sW[F2 * F3];  // 96*40*4 = 15360 B
    for (int i = threadIdx.x; i < F2 * F3; i += blockDim.x) sW[i] = W3[i];
    __syncthreads();
    int warp = (blockIdx.x * blockDim.x + threadIdx.x) >> 5;
    int lane = threadIdx.x & 31;
    if (warp >= N_NODES) return;
    const float* xr = g_agg3 + (size_t)warp * F2;
    float acc0 = b3[lane];                              // cols 0..31
    float acc1 = (lane < 8) ? b3[lane + 32] : 0.f;      // cols 32..39
#pragma unroll 4
    for (int k = 0; k < F2; k++) {
        float a = __ldg(xr + k);
        acc0 += a * sW[k * F3 + lane];
        if (lane < 8) acc1 += a * sW[k * F3 + lane + 32];
    }
    float m = fmaxf(acc0, (lane < 8) ? acc1 : -INFINITY);
#pragma unroll
    for (int o = 16; o > 0; o >>= 1) m = fmaxf(m, __shfl_xor_sync(0xffffffffu, m, o));
    float s = expf(acc0 - m) + ((lane < 8) ? expf(acc1 - m) : 0.f);
#pragma unroll
    for (int o = 16; o > 0; o >>= 1) s += __shfl_xor_sync(0xffffffffu, s, o);
    float l = logf(s);
    float* orow = out + (size_t)warp * F3;
    orow[lane] = acc0 - m - l;
    if (lane < 8) orow[lane + 32] = acc1 - m - l;
}

// ---------------- launch ----------------
extern "C" void kernel_launch(void* const* d_in, const int* in_sizes, int n_in,
                              void* d_out, int out_size) {
    const float* x  = (const float*)d_in[0];
    const float* W1 = (const float*)d_in[1];
    const float* b1 = (const float*)d_in[2];
    const float* W2 = (const float*)d_in[3];
    const float* b2 = (const float*)d_in[4];
    const float* W3 = (const float*)d_in[5];
    const float* b3 = (const float*)d_in[6];
    const int*   ei = (const int*)d_in[7];
    float* out = (float*)d_out;

    float *p_agg1, *p_h1, *p_agg2, *p_h2;
    cudaGetSymbolAddress((void**)&p_agg1, g_agg1);
    cudaGetSymbolAddress((void**)&p_h1,   g_h1);
    cudaGetSymbolAddress((void**)&p_agg2, g_agg2);
    cudaGetSymbolAddress((void**)&p_h2,   g_h2);
    float* p_agg3;
    cudaGetSymbolAddress((void**)&p_agg3, g_agg3);

    detect_kernel<<<1, 32>>>(ei);
    zero_deg_kernel<<<(N_NODES + 255) / 256, 256>>>();
    hist_kernel<<<(N_EDGES + 255) / 256, 256>>>(ei);
    block_sum_kernel<<<NB, 1024>>>();
    scan_bsums_kernel<<<1, 64>>>();
    local_scan_kernel<<<NB, 1024>>>();
    scatter_kernel<<<(N_EDGES + 255) / 256, 256>>>(ei);

    const int agg_grid = (N_NODES * 32 + 255) / 256;

    // layer 1: aggregate(x) -> agg1 ; relu(agg1 @ W1 + b1) -> h1
    agg_kernel<F0><<<agg_grid, 256>>>(x, p_agg1);
    gemm_kernel<F0, F1, true><<<(N_NODES + 31) / 32, dim3(F1 / 4, 8)>>>(p_agg1, W1, b1, p_h1);

    // layer 2
    agg_kernel<F1><<<agg_grid, 256>>>(p_h1, p_agg2);
    gemm_kernel<F1, F2, true><<<(N_NODES + 31) / 32, dim3(F2 / 4, 8)>>>(p_agg2, W2, b2, p_h2);

    // layer 3 + log_softmax
    agg_kernel<F2><<<agg_grid, 256>>>(p_h2, p_agg3);
    final_kernel<<<agg_grid, 256>>>(W3, b3, out);
}

// round 3
// speedup vs baseline: 1.6875x; 1.0798x over previous
#include <cuda_runtime.h>
#include <math.h>

#define N_NODES 50000
#define N_EDGES 800000
#define F0 128
#define F1 96
#define F2 96
#define F3 40
#define NB ((N_NODES + 1023) / 1024)   // 49 scan blocks

// ---------------- scratch (static device globals; no allocation) ----------------
__device__ int   g_is64;
__device__ int   g_deg[N_NODES];
__device__ int   g_cur[N_NODES];
__device__ int   g_off[N_NODES + 1];
__device__ int   g_csr[N_EDGES];
__device__ int   g_bsum[NB];
__device__ int   g_boff[NB];
__device__ float g_t1[(size_t)N_NODES * F1];   // x @ W1
__device__ float g_h1[(size_t)N_NODES * F1];   // relu(agg(t1)+b1)
__device__ float g_t2[(size_t)N_NODES * F2];   // h1 @ W2
__device__ float g_h2[(size_t)N_NODES * F2];   // relu(agg(t2)+b2)
__device__ float g_t3[(size_t)N_NODES * F3];   // h2 @ W3

// ---------------- edge-index dtype detection (int64 vs int32) ----------------
__global__ void detect_kernel(const int* __restrict__ ei) {
    int lane = threadIdx.x & 31;
    int acc = 0;
#pragma unroll
    for (int j = 0; j < 4; j++) acc |= ei[1 + 2 * (lane * 4 + j)];
#pragma unroll
    for (int o = 16; o > 0; o >>= 1) acc |= __shfl_xor_sync(0xffffffffu, acc, o);
    if (lane == 0) g_is64 = (acc == 0) ? 1 : 0;
}

__device__ __forceinline__ int edge_src(const int* ei, int e, int is64) {
    return is64 ? ei[2 * e] : ei[e];
}
__device__ __forceinline__ int edge_dst(const int* ei, int e, int is64) {
    return is64 ? ei[2 * (N_EDGES + e)] : ei[N_EDGES + e];
}

// ---------------- CSR build ----------------
__global__ void zero_deg_kernel() {
    int i = blockIdx.x * blockDim.x + threadIdx.x;
    if (i < N_NODES) g_deg[i] = 0;
}

__global__ void hist_kernel(const int* __restrict__ ei) {
    int e = blockIdx.x * blockDim.x + threadIdx.x;
    if (e >= N_EDGES) return;
    int is64 = g_is64;
    atomicAdd(&g_deg[edge_dst(ei, e, is64)], 1);
}

__global__ void block_sum_kernel() {
    __shared__ int wsum[32];
    int i = blockIdx.x * 1024 + threadIdx.x;
    int v = (i < N_NODES) ? g_deg[i] : 0;
    int lane = threadIdx.x & 31, w = threadIdx.x >> 5;
#pragma unroll
    for (int o = 16; o > 0; o >>= 1) v += __shfl_xor_sync(0xffffffffu, v, o);
    if (lane == 0) wsum[w] = v;
    __syncthreads();
    if (w == 0) {
        int s = wsum[lane];
#pragma unroll
        for (int o = 16; o > 0; o >>= 1) s += __shfl_xor_sync(0xffffffffu, s, o);
        if (lane == 0) g_bsum[blockIdx.x] = s;
    }
}

__global__ void scan_bsums_kernel() {   // 1 block, 64 threads, NB<=64
    __shared__ int sh[64];
    int t = threadIdx.x;
    int v = (t < NB) ? g_bsum[t] : 0;
    sh[t] = v;
    __syncthreads();
#pragma unroll
    for (int s = 1; s < 64; s <<= 1) {
        int u = (t >= s) ? sh[t - s] : 0;
        __syncthreads();
        sh[t] += u;
        __syncthreads();
    }
    if (t < NB) g_boff[t] = sh[t] - v;   // exclusive
}

__global__ void local_scan_kernel() {
    __shared__ int wsum[32];
    int i = blockIdx.x * 1024 + threadIdx.x;
    int v = (i < N_NODES) ? g_deg[i] : 0;
    int lane = threadIdx.x & 31, w = threadIdx.x >> 5;
    int incl = v;
#pragma unroll
    for (int o = 1; o < 32; o <<= 1) {
        int t = __shfl_up_sync(0xffffffffu, incl, o);
        if (lane >= o) incl += t;
    }
    if (lane == 31) wsum[w] = incl;
    __syncthreads();
    if (w == 0) {
        int s = wsum[lane];
#pragma unroll
        for (int o = 1; o < 32; o <<= 1) {
            int t = __shfl_up_sync(0xffffffffu, s, o);
            if (lane >= o) s += t;
        }
        wsum[lane] = s;
    }
    __syncthreads();
    int add = ((w > 0) ? wsum[w - 1] : 0) + g_boff[blockIdx.x];
    incl += add;
    if (i < N_NODES) {
        g_off[i + 1] = incl;
        g_cur[i]     = incl - v;
    }
    if (i == 0) g_off[0] = 0;
}

__global__ void scatter_kernel(const int* __restrict__ ei) {
    int e = blockIdx.x * blockDim.x + threadIdx.x;
    if (e >= N_EDGES) return;
    int is64 = g_is64;
    int d = edge_dst(ei, e, is64);
    int s = edge_src(ei, e, is64);
    int p = atomicAdd(&g_cur[d], 1);
    g_csr[p] = s;
}

// ---------------- dense linear (no bias): W in shared, 4 rows/thread ----------------
template <int K, int M>
__global__ void gemm_kernel(const float* __restrict__ X, const float* __restrict__ W,
                            float* __restrict__ Y) {
    constexpr int M4  = M / 4;
    constexpr int YR  = 8;
    constexpr int RPT = 4;
    constexpr int ROWS = YR * RPT;  // 32 rows per block
    __shared__ float4 sW[K * M4];
    int tid = threadIdx.y * M4 + threadIdx.x;
    for (int i = tid; i < K * M4; i += M4 * YR) sW[i] = ((const float4*)W)[i];
    __syncthreads();

    int cg = threadIdx.x;
    int row0 = blockIdx.x * ROWS + threadIdx.y;
    float4 acc[RPT];
    const float* xr[RPT];
    bool valid[RPT];
#pragma unroll
    for (int r = 0; r < RPT; r++) {
        int row = row0 + r * YR;
        valid[r] = (row < N_NODES);
        int rc = valid[r] ? row : (N_NODES - 1);
        xr[r] = X + (size_t)rc * K;
        acc[r] = make_float4(0.f, 0.f, 0.f, 0.f);
    }
#pragma unroll 4
    for (int k = 0; k < K; k++) {
        float4 w = sW[k * M4 + cg];
#pragma unroll
        for (int r = 0; r < RPT; r++) {
            float a = __ldg(xr[r] + k);
            acc[r].x += a * w.x; acc[r].y += a * w.y;
            acc[r].z += a * w.z; acc[r].w += a * w.w;
        }
    }
#pragma unroll
    for (int r = 0; r < RPT; r++) {
        if (!valid[r]) continue;
        ((float4*)(Y + (size_t)(row0 + r * YR) * M))[cg] = acc[r];
    }
}

// ---------------- gather aggregation + fused epilogue ----------------
// EPI 0: relu(acc + bias)   EPI 1: log_softmax(acc + bias)
template <int D, int EPI>
__global__ void agg_kernel(const float* __restrict__ xin, const float* __restrict__ bias,
                           float* __restrict__ xout) {
    int gw   = (blockIdx.x * blockDim.x + threadIdx.x) >> 5;
    int lane = threadIdx.x & 31;
    if (gw >= N_NODES) return;
    constexpr int D4 = D / 4;
    float4 acc = make_float4(0.f, 0.f, 0.f, 0.f);
    int beg = g_off[gw], end = g_off[gw + 1];
    int e = beg;
    for (; e + 3 < end; e += 4) {
        int s0 = g_csr[e], s1 = g_csr[e + 1], s2 = g_csr[e + 2], s3 = g_csr[e + 3];
        if (lane < D4) {
            float4 v0 = __ldg((const float4*)(xin + (size_t)s0 * D) + lane);
            float4 v1 = __ldg((const float4*)(xin + (size_t)s1 * D) + lane);
            float4 v2 = __ldg((const float4*)(xin + (size_t)s2 * D) + lane);
            float4 v3 = __ldg((const float4*)(xin + (size_t)s3 * D) + lane);
            acc.x += (v0.x + v1.x) + (v2.x + v3.x);
            acc.y += (v0.y + v1.y) + (v2.y + v3.y);
            acc.z += (v0.z + v1.z) + (v2.z + v3.z);
            acc.w += (v0.w + v1.w) + (v2.w + v3.w);
        }
    }
    for (; e < end; e++) {
        int s0 = g_csr[e];
        if (lane < D4) {
            float4 v0 = __ldg((const float4*)(xin + (size_t)s0 * D) + lane);
            acc.x += v0.x; acc.y += v0.y; acc.z += v0.z; acc.w += v0.w;
        }
    }
    float4 bb = (lane < D4) ? ((const float4*)bias)[lane] : make_float4(0.f, 0.f, 0.f, 0.f);
    acc.x += bb.x; acc.y += bb.y; acc.z += bb.z; acc.w += bb.w;

    if (EPI == 0) {
        if (lane < D4) {
            acc.x = fmaxf(acc.x, 0.f); acc.y = fmaxf(acc.y, 0.f);
            acc.z = fmaxf(acc.z, 0.f); acc.w = fmaxf(acc.w, 0.f);
            ((float4*)(xout + (size_t)gw * D))[lane] = acc;
        }
    } else {
        // log_softmax across D values held by lanes 0..D4-1
        float m = (lane < D4)
                ? fmaxf(fmaxf(acc.x, acc.y), fmaxf(acc.z, acc.w))
                : -INFINITY;
#pragma unroll
        for (int o = 16; o > 0; o >>= 1) m = fmaxf(m, __shfl_xor_sync(0xffffffffu, m, o));
        float s = (lane < D4)
                ? (expf(acc.x - m) + expf(acc.y - m)) + (expf(acc.z - m) + expf(acc.w - m))
                : 0.f;
#pragma unroll
        for (int o = 16; o > 0; o >>= 1) s += __shfl_xor_sync(0xffffffffu, s, o);
        float l = m + logf(s);
        if (lane < D4) {
            acc.x -= l; acc.y -= l; acc.z -= l; acc.w -= l;
            ((float4*)(xout + (size_t)gw * D))[lane] = acc;
        }
    }
}

// ---------------- launch ----------------
extern "C" void kernel_launch(void* const* d_in, const int* in_sizes, int n_in,
                              void* d_out, int out_size) {
    const float* x  = (const float*)d_in[0];
    const float* W1 = (const float*)d_in[1];
    const float* b1 = (const float*)d_in[2];
    const float* W2 = (const float*)d_in[3];
    const float* b2 = (const float*)d_in[4];
    const float* W3 = (const float*)d_in[5];
    const float* b3 = (const float*)d_in[6];
    const int*   ei = (const int*)d_in[7];
    float* out = (float*)d_out;

    float *p_t1, *p_h1, *p_t2, *p_h2, *p_t3;
    cudaGetSymbolAddress((void**)&p_t1, g_t1);
    cudaGetSymbolAddress((void**)&p_h1, g_h1);
    cudaGetSymbolAddress((void**)&p_t2, g_t2);
    cudaGetSymbolAddress((void**)&p_h2, g_h2);
    cudaGetSymbolAddress((void**)&p_t3, g_t3);

    detect_kernel<<<1, 32>>>(ei);
    zero_deg_kernel<<<(N_NODES + 255) / 256, 256>>>();
    hist_kernel<<<(N_EDGES + 255) / 256, 256>>>(ei);
    block_sum_kernel<<<NB, 1024>>>();
    scan_bsums_kernel<<<1, 64>>>();
    local_scan_kernel<<<NB, 1024>>>();
    scatter_kernel<<<(N_EDGES + 255) / 256, 256>>>(ei);

    const int agg_grid  = (N_NODES * 32 + 255) / 256;
    const int gemm_grid = (N_NODES + 31) / 32;

    // layer 1 (transform first): t1 = x @ W1 ; h1 = relu(agg(t1) + b1)
    gemm_kernel<F0, F1><<<gemm_grid, dim3(F1 / 4, 8)>>>(x, W1, p_t1);
    agg_kernel<F1, 0><<<agg_grid, 256>>>(p_t1, b1, p_h1);

    // layer 2: t2 = h1 @ W2 ; h2 = relu(agg(t2) + b2)
    gemm_kernel<F1, F2><<<gemm_grid, dim3(F2 / 4, 8)>>>(p_h1, W2, p_t2);
    agg_kernel<F2, 0><<<agg_grid, 256>>>(p_t2, b2, p_h2);

    // layer 3: t3 = h2 @ W3 ; out = log_softmax(agg(t3) + b3)
    gemm_kernel<F2, F3><<<gemm_grid, dim3(F3 / 4, 8)>>>(p_h2, W3, p_t3);
    agg_kernel<F3, 1><<<agg_grid, 256>>>(p_t3, b3, out);
}

// round 4
// speedup vs baseline: 1.8014x; 1.0675x over previous
#include <cuda_runtime.h>
#include <math.h>

#define N_NODES 50000
#define N_EDGES 800000
#define F0 128
#define F1 96
#define F2 96
#define F3 40
#define NB ((N_NODES + 1023) / 1024)   // 49 scan blocks

// ---------------- scratch (static device globals; no allocation) ----------------
__device__ int   g_deg[N_NODES];
__device__ int   g_cur[N_NODES];
__device__ int   g_off[N_NODES + 1];
__device__ int   g_csr[N_EDGES];
__device__ int   g_bsum[NB];
__device__ float g_t1[(size_t)N_NODES * F1];   // x @ W1
__device__ float g_h1[(size_t)N_NODES * F1];   // relu(agg(t1)+b1)
__device__ float g_t2[(size_t)N_NODES * F2];   // h1 @ W2
__device__ float g_h2[(size_t)N_NODES * F2];   // relu(agg(t2)+b2)
__device__ float g_t3[(size_t)N_NODES * F3];   // h2 @ W3

// ---------------- inline edge-index dtype detection (int64 vs int32) ----------------
// int64 values < 50000 -> every odd 32-bit word of the first 128 values is 0.
__device__ __forceinline__ int block_detect_is64(const int* __restrict__ ei, int* s_flag) {
    if (threadIdx.x < 32) {
        int acc = 0;
#pragma unroll
        for (int j = 0; j < 4; j++) acc |= ei[1 + 2 * (threadIdx.x * 4 + j)];
#pragma unroll
        for (int o = 16; o > 0; o >>= 1) acc |= __shfl_xor_sync(0xffffffffu, acc, o);
        if (threadIdx.x == 0) *s_flag = (acc == 0) ? 1 : 0;
    }
    __syncthreads();
    return *s_flag;
}

__device__ __forceinline__ int edge_src(const int* ei, int e, int is64) {
    return is64 ? ei[2 * e] : ei[e];
}
__device__ __forceinline__ int edge_dst(const int* ei, int e, int is64) {
    return is64 ? ei[2 * (N_EDGES + e)] : ei[N_EDGES + e];
}

// ---------------- CSR build ----------------
__global__ void zero_deg_kernel() {
    int i = blockIdx.x * blockDim.x + threadIdx.x;
    if (i < N_NODES) g_deg[i] = 0;
}

__global__ void hist_kernel(const int* __restrict__ ei) {
    __shared__ int s_is64;
    int is64 = block_detect_is64(ei, &s_is64);
    int e = blockIdx.x * blockDim.x + threadIdx.x;
    if (e >= N_EDGES) return;
    atomicAdd(&g_deg[edge_dst(ei, e, is64)], 1);
}

__global__ void block_sum_kernel() {
    __shared__ int wsum[32];
    int i = blockIdx.x * 1024 + threadIdx.x;
    int v = (i < N_NODES) ? g_deg[i] : 0;
    int lane = threadIdx.x & 31, w = threadIdx.x >> 5;
#pragma unroll
    for (int o = 16; o > 0; o >>= 1) v += __shfl_xor_sync(0xffffffffu, v, o);
    if (lane == 0) wsum[w] = v;
    __syncthreads();
    if (w == 0) {
        int s = wsum[lane];
#pragma unroll
        for (int o = 16; o > 0; o >>= 1) s += __shfl_xor_sync(0xffffffffu, s, o);
        if (lane == 0) g_bsum[blockIdx.x] = s;
    }
}

// local scan; each block redundantly computes its global offset from g_bsum
__global__ void local_scan_kernel() {
    __shared__ int sb[64];
    __shared__ int wsum[32];
    int t = threadIdx.x;
    if (t < 64) sb[t] = (t < NB) ? g_bsum[t] : 0;
    __syncthreads();
#pragma unroll
    for (int s = 1; s < 64; s <<= 1) {
        int u = 0;
        if (t < 64 && t >= s) u = sb[t - s];
        __syncthreads();
        if (t < 64) sb[t] += u;
        __syncthreads();
    }
    int boff = (blockIdx.x > 0) ? sb[blockIdx.x - 1] : 0;

    int i = blockIdx.x * 1024 + t;
    int v = (i < N_NODES) ? g_deg[i] : 0;
    int lane = t & 31, w = t >> 5;
    int incl = v;
#pragma unroll
    for (int o = 1; o < 32; o <<= 1) {
        int u = __shfl_up_sync(0xffffffffu, incl, o);
        if (lane >= o) incl += u;
    }
    if (lane == 31) wsum[w] = incl;
    __syncthreads();
    if (w == 0) {
        int s = wsum[lane];
#pragma unroll
        for (int o = 1; o < 32; o <<= 1) {
            int u = __shfl_up_sync(0xffffffffu, s, o);
            if (lane >= o) s += u;
        }
        wsum[lane] = s;
    }
    __syncthreads();
    int add = ((w > 0) ? wsum[w - 1] : 0) + boff;
    incl += add;
    if (i < N_NODES) {
        g_off[i + 1] = incl;
        g_cur[i]     = incl - v;
    }
    if (i == 0) g_off[0] = 0;
}

__global__ void scatter_kernel(const int* __restrict__ ei) {
    __shared__ int s_is64;
    int is64 = block_detect_is64(ei, &s_is64);
    int e = blockIdx.x * blockDim.x + threadIdx.x;
    if (e >= N_EDGES) return;
    int d = edge_dst(ei, e, is64);
    int s = edge_src(ei, e, is64);
    int p = atomicAdd(&g_cur[d], 1);
    g_csr[p] = s;
}

// ---------------- dense linear (no bias): W in shared, 4 rows/thread ----------------
template <int K, int M>
__global__ void gemm_kernel(const float* __restrict__ X, const float* __restrict__ W,
                            float* __restrict__ Y) {
    constexpr int M4  = M / 4;
    constexpr int YR  = 8;
    constexpr int RPT = 4;
    constexpr int ROWS = YR * RPT;  // 32 rows per block
    __shared__ float4 sW[K * M4];
    int tid = threadIdx.y * M4 + threadIdx.x;
    for (int i = tid; i < K * M4; i += M4 * YR) sW[i] = ((const float4*)W)[i];
    __syncthreads();

    int cg = threadIdx.x;
    int row0 = blockIdx.x * ROWS + threadIdx.y;
    float4 acc[RPT];
    const float* xr[RPT];
    bool valid[RPT];
#pragma unroll
    for (int r = 0; r < RPT; r++) {
        int row = row0 + r * YR;
        valid[r] = (row < N_NODES);
        int rc = valid[r] ? row : (N_NODES - 1);
        xr[r] = X + (size_t)rc * K;
        acc[r] = make_float4(0.f, 0.f, 0.f, 0.f);
    }
#pragma unroll 4
    for (int k = 0; k < K; k++) {
        float4 w = sW[k * M4 + cg];
#pragma unroll
        for (int r = 0; r < RPT; r++) {
            float a = __ldg(xr[r] + k);
            acc[r].x += a * w.x; acc[r].y += a * w.y;
            acc[r].z += a * w.z; acc[r].w += a * w.w;
        }
    }
#pragma unroll
    for (int r = 0; r < RPT; r++) {
        if (!valid[r]) continue;
        ((float4*)(Y + (size_t)(row0 + r * YR) * M))[cg] = acc[r];
    }
}

// ---------------- gather aggregation + fused epilogue ----------------
// EPI 0: relu(acc + bias)   EPI 1: log_softmax(acc + bias)
template <int D, int EPI>
__global__ void agg_kernel(const float* __restrict__ xin, const float* __restrict__ bias,
                           float* __restrict__ xout) {
    int gw   = (blockIdx.x * blockDim.x + threadIdx.x) >> 5;
    int lane = threadIdx.x & 31;
    if (gw >= N_NODES) return;
    constexpr int D4 = D / 4;
    float4 acc = make_float4(0.f, 0.f, 0.f, 0.f);
    int beg = g_off[gw], end = g_off[gw + 1];
    int e = beg;
    for (; e + 3 < end; e += 4) {
        int s0 = g_csr[e], s1 = g_csr[e + 1], s2 = g_csr[e + 2], s3 = g_csr[e + 3];
        if (lane < D4) {
            float4 v0 = __ldg((const float4*)(xin + (size_t)s0 * D) + lane);
            float4 v1 = __ldg((const float4*)(xin + (size_t)s1 * D) + lane);
            float4 v2 = __ldg((const float4*)(xin + (size_t)s2 * D) + lane);
            float4 v3 = __ldg((const float4*)(xin + (size_t)s3 * D) + lane);
            acc.x += (v0.x + v1.x) + (v2.x + v3.x);
            acc.y += (v0.y + v1.y) + (v2.y + v3.y);
            acc.z += (v0.z + v1.z) + (v2.z + v3.z);
            acc.w += (v0.w + v1.w) + (v2.w + v3.w);
        }
    }
    for (; e < end; e++) {
        int s0 = g_csr[e];
        if (lane < D4) {
            float4 v0 = __ldg((const float4*)(xin + (size_t)s0 * D) + lane);
            acc.x += v0.x; acc.y += v0.y; acc.z += v0.z; acc.w += v0.w;
        }
    }
    float4 bb = (lane < D4) ? ((const float4*)bias)[lane] : make_float4(0.f, 0.f, 0.f, 0.f);
    acc.x += bb.x; acc.y += bb.y; acc.z += bb.z; acc.w += bb.w;

    if (EPI == 0) {
        if (lane < D4) {
            acc.x = fmaxf(acc.x, 0.f); acc.y = fmaxf(acc.y, 0.f);
            acc.z = fmaxf(acc.z, 0.f); acc.w = fmaxf(acc.w, 0.f);
            ((float4*)(xout + (size_t)gw * D))[lane] = acc;
        }
    } else {
        float m = (lane < D4)
                ? fmaxf(fmaxf(acc.x, acc.y), fmaxf(acc.z, acc.w))
                : -INFINITY;
#pragma unroll
        for (int o = 16; o > 0; o >>= 1) m = fmaxf(m, __shfl_xor_sync(0xffffffffu, m, o));
        float s = (lane < D4)
                ? (expf(acc.x - m) + expf(acc.y - m)) + (expf(acc.z - m) + expf(acc.w - m))
                : 0.f;
#pragma unroll
        for (int o = 16; o > 0; o >>= 1) s += __shfl_xor_sync(0xffffffffu, s, o);
        float l = m + logf(s);
        if (lane < D4) {
            acc.x -= l; acc.y -= l; acc.z -= l; acc.w -= l;
            ((float4*)(xout + (size_t)gw * D))[lane] = acc;
        }
    }
}

// ---------------- launch ----------------
extern "C" void kernel_launch(void* const* d_in, const int* in_sizes, int n_in,
                              void* d_out, int out_size) {
    const float* x  = (const float*)d_in[0];
    const float* W1 = (const float*)d_in[1];
    const float* b1 = (const float*)d_in[2];
    const float* W2 = (const float*)d_in[3];
    const float* b2 = (const float*)d_in[4];
    const float* W3 = (const float*)d_in[5];
    const float* b3 = (const float*)d_in[6];
    const int*   ei = (const int*)d_in[7];
    float* out = (float*)d_out;

    float *p_t1, *p_h1, *p_t2, *p_h2, *p_t3;
    cudaGetSymbolAddress((void**)&p_t1, g_t1);
    cudaGetSymbolAddress((void**)&p_h1, g_h1);
    cudaGetSymbolAddress((void**)&p_t2, g_t2);
    cudaGetSymbolAddress((void**)&p_h2, g_h2);
    cudaGetSymbolAddress((void**)&p_t3, g_t3);

    // one-time host resources (no device memory). Work per call is identical.
    static cudaStream_t s2 = nullptr;
    static cudaEvent_t ev_fork = nullptr, ev_join = nullptr;
    if (!s2) {
        cudaStreamCreateWithFlags(&s2, cudaStreamNonBlocking);
        cudaEventCreateWithFlags(&ev_fork, cudaEventDisableTiming);
        cudaEventCreateWithFlags(&ev_join, cudaEventDisableTiming);
    }

    // fork: CSR build chain on s2, concurrent with GEMM1 on the main stream
    cudaEventRecord(ev_fork, 0);
    cudaStreamWaitEvent(s2, ev_fork, 0);

    zero_deg_kernel<<<(N_NODES + 255) / 256, 256, 0, s2>>>();
    hist_kernel<<<(N_EDGES + 255) / 256, 256, 0, s2>>>(ei);
    block_sum_kernel<<<NB, 1024, 0, s2>>>();
    local_scan_kernel<<<NB, 1024, 0, s2>>>();
    scatter_kernel<<<(N_EDGES + 255) / 256, 256, 0, s2>>>(ei);
    cudaEventRecord(ev_join, s2);

    const int agg_grid  = (N_NODES * 32 + 255) / 256;
    const int gemm_grid = (N_NODES + 31) / 32;

    // main stream: t1 = x @ W1 (independent of CSR)
    gemm_kernel<F0, F1><<<gemm_grid, dim3(F1 / 4, 8)>>>(x, W1, p_t1);

    // join: aggregation needs CSR
    cudaStreamWaitEvent(0, ev_join, 0);

    // layer 1: h1 = relu(agg(t1) + b1)
    agg_kernel<F1, 0><<<agg_grid, 256>>>(p_t1, b1, p_h1);
    // layer 2
    gemm_kernel<F1, F2><<<gemm_grid, dim3(F2 / 4, 8)>>>(p_h1, W2, p_t2);
    agg_kernel<F2, 0><<<agg_grid, 256>>>(p_t2, b2, p_h2);
    // layer 3 + log_softmax
    gemm_kernel<F2, F3><<<gemm_grid, dim3(F3 / 4, 8)>>>(p_h2, W3, p_t3);
    agg_kernel<F3, 1><<<agg_grid, 256>>>(p_t3, b3, out);
}

// round 5
// speedup vs baseline: 2.3740x; 1.3178x over previous
#include <cuda_runtime.h>
#include <math.h>
#include <stdint.h>

#define N_NODES 50000
#define N_EDGES 800000
#define F0 128
#define F1 96
#define F2 96
#define F3 40
#define NB ((N_NODES + 1023) / 1024)   // 49 scan blocks

// ---------------- scratch (static device globals; no allocation) ----------------
__device__ int   g_deg[N_NODES];
__device__ int   g_cur[N_NODES];
__device__ int   g_off[N_NODES + 1];
__device__ int   g_csr[N_EDGES];
__device__ int   g_bsum[NB];
__device__ float g_t1[(size_t)N_NODES * F1];   // x @ W1
__device__ float g_h1[(size_t)N_NODES * F1];   // relu(agg(t1)+b1)
__device__ float g_t2[(size_t)N_NODES * F2];   // h1 @ W2
__device__ float g_h2[(size_t)N_NODES * F2];   // relu(agg(t2)+b2)
__device__ float g_t3[(size_t)N_NODES * F3];   // h2 @ W3

// ---------------- inline edge-index dtype detection (int64 vs int32) ----------------
__device__ __forceinline__ int block_detect_is64(const int* __restrict__ ei, int* s_flag) {
    if (threadIdx.x < 32) {
        int acc = 0;
#pragma unroll
        for (int j = 0; j < 4; j++) acc |= ei[1 + 2 * (threadIdx.x * 4 + j)];
#pragma unroll
        for (int o = 16; o > 0; o >>= 1) acc |= __shfl_xor_sync(0xffffffffu, acc, o);
        if (threadIdx.x == 0) *s_flag = (acc == 0) ? 1 : 0;
    }
    __syncthreads();
    return *s_flag;
}

__device__ __forceinline__ int edge_src(const int* ei, int e, int is64) {
    return is64 ? ei[2 * e] : ei[e];
}
__device__ __forceinline__ int edge_dst(const int* ei, int e, int is64) {
    return is64 ? ei[2 * (N_EDGES + e)] : ei[N_EDGES + e];
}

// ---------------- CSR build ----------------
__global__ void zero_deg_kernel() {
    int i = blockIdx.x * blockDim.x + threadIdx.x;
    if (i < N_NODES) g_deg[i] = 0;
}

__global__ void hist_kernel(const int* __restrict__ ei) {
    __shared__ int s_is64;
    int is64 = block_detect_is64(ei, &s_is64);
    int e = blockIdx.x * blockDim.x + threadIdx.x;
    if (e >= N_EDGES) return;
    atomicAdd(&g_deg[edge_dst(ei, e, is64)], 1);
}

__global__ void block_sum_kernel() {
    __shared__ int wsum[32];
    int i = blockIdx.x * 1024 + threadIdx.x;
    int v = (i < N_NODES) ? g_deg[i] : 0;
    int lane = threadIdx.x & 31, w = threadIdx.x >> 5;
#pragma unroll
    for (int o = 16; o > 0; o >>= 1) v += __shfl_xor_sync(0xffffffffu, v, o);
    if (lane == 0) wsum[w] = v;
    __syncthreads();
    if (w == 0) {
        int s = wsum[lane];
#pragma unroll
        for (int o = 16; o > 0; o >>= 1) s += __shfl_xor_sync(0xffffffffu, s, o);
        if (lane == 0) g_bsum[blockIdx.x] = s;
    }
}

__global__ void local_scan_kernel() {
    __shared__ int sb[64];
    __shared__ int wsum[32];
    int t = threadIdx.x;
    if (t < 64) sb[t] = (t < NB) ? g_bsum[t] : 0;
    __syncthreads();
#pragma unroll
    for (int s = 1; s < 64; s <<= 1) {
        int u = 0;
        if (t < 64 && t >= s) u = sb[t - s];
        __syncthreads();
        if (t < 64) sb[t] += u;
        __syncthreads();
    }
    int boff = (blockIdx.x > 0) ? sb[blockIdx.x - 1] : 0;

    int i = blockIdx.x * 1024 + t;
    int v = (i < N_NODES) ? g_deg[i] : 0;
    int lane = t & 31, w = t >> 5;
    int incl = v;
#pragma unroll
    for (int o = 1; o < 32; o <<= 1) {
        int u = __shfl_up_sync(0xffffffffu, incl, o);
        if (lane >= o) incl += u;
    }
    if (lane == 31) wsum[w] = incl;
    __syncthreads();
    if (w == 0) {
        int s = wsum[lane];
#pragma unroll
        for (int o = 1; o < 32; o <<= 1) {
            int u = __shfl_up_sync(0xffffffffu, s, o);
            if (lane >= o) s += u;
        }
        wsum[lane] = s;
    }
    __syncthreads();
    int add = ((w > 0) ? wsum[w - 1] : 0) + boff;
    incl += add;
    if (i < N_NODES) {
        g_off[i + 1] = incl;
        g_cur[i]     = incl - v;
    }
    if (i == 0) g_off[0] = 0;
}

__global__ void scatter_kernel(const int* __restrict__ ei) {
    __shared__ int s_is64;
    int is64 = block_detect_is64(ei, &s_is64);
    int e = blockIdx.x * blockDim.x + threadIdx.x;
    if (e >= N_EDGES) return;
    int d = edge_dst(ei, e, is64);
    int s = edge_src(ei, e, is64);
    int p = atomicAdd(&g_cur[d], 1);
    g_csr[p] = s;
}

// ---------------- 3xTF32 tensor-core GEMM: Y[M,N] = X[M,K] @ W[K,N] ----------------
__device__ __forceinline__ uint32_t f2tf32(float f) {
    uint32_t r;
    asm("cvt.rna.tf32.f32 %0, %1;" : "=r"(r) : "f"(f));
    return r;
}

__device__ __forceinline__ void mma8(float c[4], const uint32_t a[4],
                                     uint32_t b0, uint32_t b1) {
    asm volatile(
        "mma.sync.aligned.m16n8k8.row.col.f32.tf32.tf32.f32 "
        "{%0,%1,%2,%3}, {%4,%5,%6,%7}, {%8,%9}, {%0,%1,%2,%3};"
        : "+f"(c[0]), "+f"(c[1]), "+f"(c[2]), "+f"(c[3])
        : "r"(a[0]), "r"(a[1]), "r"(a[2]), "r"(a[3]), "r"(b0), "r"(b1));
}

// block: 256 threads = 8 warps, 16 rows/warp -> 128 rows/block.
// W (hi/lo tf32 split) staged in dynamic smem with stride PS == 8 (mod 32)
// -> B-fragment LDS is bank-conflict-free.
template <int K, int N>
__global__ void __launch_bounds__(256) mma_gemm_kernel(
        const float* __restrict__ X, const float* __restrict__ W,
        float* __restrict__ Y) {
    constexpr int NT  = N / 8;
    constexpr int PAD = (8 - (N % 32) + 32) % 32;
    constexpr int PS  = N + PAD;
    extern __shared__ uint32_t smem[];
    uint32_t* sHi = smem;
    uint32_t* sLo = smem + K * PS;

    int tid = threadIdx.x;
    for (int i = tid; i < K * N; i += 256) {
        int k = i / N, n = i % N;
        float w = __ldg(W + i);
        uint32_t hi = f2tf32(w);
        sHi[k * PS + n] = hi;
        sLo[k * PS + n] = f2tf32(w - __uint_as_float(hi));
    }
    __syncthreads();

    int warp = tid >> 5, lane = tid & 31;
    int tig = lane & 3, grp = lane >> 2;
    int row0 = blockIdx.x * 128 + warp * 16;
    int r0 = row0 + grp, r1 = row0 + grp + 8;
    const float* xr0 = X + (size_t)((r0 < N_NODES) ? r0 : (N_NODES - 1)) * K;
    const float* xr1 = X + (size_t)((r1 < N_NODES) ? r1 : (N_NODES - 1)) * K;

    float c[NT][4];
#pragma unroll
    for (int nt = 0; nt < NT; nt++)
#pragma unroll
        for (int j = 0; j < 4; j++) c[nt][j] = 0.f;

#pragma unroll 1
    for (int k0 = 0; k0 < K; k0 += 8) {
        float a0 = __ldg(xr0 + k0 + tig);
        float a1 = __ldg(xr1 + k0 + tig);
        float a2 = __ldg(xr0 + k0 + tig + 4);
        float a3 = __ldg(xr1 + k0 + tig + 4);
        uint32_t ahi[4] = {f2tf32(a0), f2tf32(a1), f2tf32(a2), f2tf32(a3)};
        uint32_t alo[4] = {f2tf32(a0 - __uint_as_float(ahi[0])),
                           f2tf32(a1 - __uint_as_float(ahi[1])),
                           f2tf32(a2 - __uint_as_float(ahi[2])),
                           f2tf32(a3 - __uint_as_float(ahi[3]))};
        const uint32_t* rHi0 = sHi + (k0 + tig) * PS + grp;
        const uint32_t* rHi1 = sHi + (k0 + tig + 4) * PS + grp;
        const uint32_t* rLo0 = sLo + (k0 + tig) * PS + grp;
        const uint32_t* rLo1 = sLo + (k0 + tig + 4) * PS + grp;
#pragma unroll
        for (int nt = 0; nt < NT; nt++) {
            uint32_t b0h = rHi0[nt * 8], b1h = rHi1[nt * 8];
            uint32_t b0l = rLo0[nt * 8], b1l = rLo1[nt * 8];
            mma8(c[nt], ahi, b0h, b1h);   // hi*hi
            mma8(c[nt], alo, b0h, b1h);   // lo*hi
            mma8(c[nt], ahi, b0l, b1l);   // hi*lo
        }
    }

#pragma unroll
    for (int nt = 0; nt < NT; nt++) {
        int col = nt * 8 + 2 * tig;
        if (r0 < N_NODES)
            *(float2*)(Y + (size_t)r0 * N + col) = make_float2(c[nt][0], c[nt][1]);
        if (r1 < N_NODES)
            *(float2*)(Y + (size_t)r1 * N + col) = make_float2(c[nt][2], c[nt][3]);
    }
}

// ---------------- gather aggregation + fused epilogue ----------------
// EPI 0: relu(acc + bias)   EPI 1: log_softmax(acc + bias)
template <int D, int EPI>
__global__ void agg_kernel(const float* __restrict__ xin, const float* __restrict__ bias,
                           float* __restrict__ xout) {
    int gw   = (blockIdx.x * blockDim.x + threadIdx.x) >> 5;
    int lane = threadIdx.x & 31;
    if (gw >= N_NODES) return;
    constexpr int D4 = D / 4;
    float4 acc = make_float4(0.f, 0.f, 0.f, 0.f);
    int beg = g_off[gw], end = g_off[gw + 1];
    int e = beg;
    for (; e + 3 < end; e += 4) {
        int s0 = g_csr[e], s1 = g_csr[e + 1], s2 = g_csr[e + 2], s3 = g_csr[e + 3];
        if (lane < D4) {
            float4 v0 = __ldg((const float4*)(xin + (size_t)s0 * D) + lane);
            float4 v1 = __ldg((const float4*)(xin + (size_t)s1 * D) + lane);
            float4 v2 = __ldg((const float4*)(xin + (size_t)s2 * D) + lane);
            float4 v3 = __ldg((const float4*)(xin + (size_t)s3 * D) + lane);
            acc.x += (v0.x + v1.x) + (v2.x + v3.x);
            acc.y += (v0.y + v1.y) + (v2.y + v3.y);
            acc.z += (v0.z + v1.z) + (v2.z + v3.z);
            acc.w += (v0.w + v1.w) + (v2.w + v3.w);
        }
    }
    for (; e < end; e++) {
        int s0 = g_csr[e];
        if (lane < D4) {
            float4 v0 = __ldg((const float4*)(xin + (size_t)s0 * D) + lane);
            acc.x += v0.x; acc.y += v0.y; acc.z += v0.z; acc.w += v0.w;
        }
    }
    float4 bb = (lane < D4) ? ((const float4*)bias)[lane] : make_float4(0.f, 0.f, 0.f, 0.f);
    acc.x += bb.x; acc.y += bb.y; acc.z += bb.z; acc.w += bb.w;

    if (EPI == 0) {
        if (lane < D4) {
            acc.x = fmaxf(acc.x, 0.f); acc.y = fmaxf(acc.y, 0.f);
            acc.z = fmaxf(acc.z, 0.f); acc.w = fmaxf(acc.w, 0.f);
            ((float4*)(xout + (size_t)gw * D))[lane] = acc;
        }
    } else {
        float m = (lane < D4)
                ? fmaxf(fmaxf(acc.x, acc.y), fmaxf(acc.z, acc.w))
                : -INFINITY;
#pragma unroll
        for (int o = 16; o > 0; o >>= 1) m = fmaxf(m, __shfl_xor_sync(0xffffffffu, m, o));
        float s = (lane < D4)
                ? (expf(acc.x - m) + expf(acc.y - m)) + (expf(acc.z - m) + expf(acc.w - m))
                : 0.f;
#pragma unroll
        for (int o = 16; o > 0; o >>= 1) s += __shfl_xor_sync(0xffffffffu, s, o);
        float l = m + logf(s);
        if (lane < D4) {
            acc.x -= l; acc.y -= l; acc.z -= l; acc.w -= l;
            ((float4*)(xout + (size_t)gw * D))[lane] = acc;
        }
    }
}

// ---------------- launch ----------------
extern "C" void kernel_launch(void* const* d_in, const int* in_sizes, int n_in,
                              void* d_out, int out_size) {
    const float* x  = (const float*)d_in[0];
    const float* W1 = (const float*)d_in[1];
    const float* b1 = (const float*)d_in[2];
    const float* W2 = (const float*)d_in[3];
    const float* b2 = (const float*)d_in[4];
    const float* W3 = (const float*)d_in[5];
    const float* b3 = (const float*)d_in[6];
    const int*   ei = (const int*)d_in[7];
    float* out = (float*)d_out;

    float *p_t1, *p_h1, *p_t2, *p_h2, *p_t3;
    cudaGetSymbolAddress((void**)&p_t1, g_t1);
    cudaGetSymbolAddress((void**)&p_h1, g_h1);
    cudaGetSymbolAddress((void**)&p_t2, g_t2);
    cudaGetSymbolAddress((void**)&p_h2, g_h2);
    cudaGetSymbolAddress((void**)&p_t3, g_t3);

    // dynamic smem sizes (hi+lo tf32 copies of W, padded stride)
    constexpr int PS1 = F1 + ((8 - (F1 % 32) + 32) % 32);   // 104
    constexpr int PS2 = F2 + ((8 - (F2 % 32) + 32) % 32);   // 104
    constexpr int PS3 = F3 + ((8 - (F3 % 32) + 32) % 32);   // 40
    const int smem1 = 2 * F0 * PS1 * 4;
    const int smem2 = 2 * F1 * PS2 * 4;
    const int smem3 = 2 * F2 * PS3 * 4;

    // one-time host resources (no device memory). Work per call is identical.
    static cudaStream_t s2 = nullptr;
    static cudaEvent_t ev_fork = nullptr, ev_join = nullptr;
    if (!s2) {
        cudaStreamCreateWithFlags(&s2, cudaStreamNonBlocking);
        cudaEventCreateWithFlags(&ev_fork, cudaEventDisableTiming);
        cudaEventCreateWithFlags(&ev_join, cudaEventDisableTiming);
        cudaFuncSetAttribute(mma_gemm_kernel<F0, F1>,
                             cudaFuncAttributeMaxDynamicSharedMemorySize, smem1);
        cudaFuncSetAttribute(mma_gemm_kernel<F1, F2>,
                             cudaFuncAttributeMaxDynamicSharedMemorySize, smem2);
        cudaFuncSetAttribute(mma_gemm_kernel<F2, F3>,
                             cudaFuncAttributeMaxDynamicSharedMemorySize, smem3);
    }

    // fork: CSR build chain on s2, concurrent with GEMM1 on the main stream
    cudaEventRecord(ev_fork, 0);
    cudaStreamWaitEvent(s2, ev_fork, 0);

    zero_deg_kernel<<<(N_NODES + 255) / 256, 256, 0, s2>>>();
    hist_kernel<<<(N_EDGES + 255) / 256, 256, 0, s2>>>(ei);
    block_sum_kernel<<<NB, 1024, 0, s2>>>();
    local_scan_kernel<<<NB, 1024, 0, s2>>>();
    scatter_kernel<<<(N_EDGES + 255) / 256, 256, 0, s2>>>(ei);
    cudaEventRecord(ev_join, s2);

    const int agg_grid  = (N_NODES * 32 + 255) / 256;
    const int gemm_grid = (N_NODES + 127) / 128;

    // main stream: t1 = x @ W1 (independent of CSR)
    mma_gemm_kernel<F0, F1><<<gemm_grid, 256, smem1>>>(x, W1, p_t1);

    // join: aggregation needs CSR
    cudaStreamWaitEvent(0, ev_join, 0);

    // layer 1: h1 = relu(agg(t1) + b1)
    agg_kernel<F1, 0><<<agg_grid, 256>>>(p_t1, b1, p_h1);
    // layer 2
    mma_gemm_kernel<F1, F2><<<gemm_grid, 256, smem2>>>(p_h1, W2, p_t2);
    agg_kernel<F2, 0><<<agg_grid, 256>>>(p_t2, b2, p_h2);
    // layer 3 + log_softmax
    mma_gemm_kernel<F2, F3><<<gemm_grid, 256, smem3>>>(p_h2, W3, p_t3);
    agg_kernel<F3, 1><<<agg_grid, 256>>>(p_t3, b3, out);
}